// round 2
// baseline (speedup 1.0000x reference)
#include <cuda_runtime.h>
#include <mma.h>
#include <cstdint>
#include <cstddef>

using namespace nvcuda;

#define BATCH 8192
#define FDIM  1024
#define HDIM  256
#define NTASK 8

// ---------------- scratch (static device globals; no allocation) ----------------
__device__ float    g_h[BATCH * HDIM];        // pre-activation h
__device__ float    g_G[HDIM * HDIM];         // Gram = W1 @ W1^T
__device__ float    g_coeffs[BATCH * NTASK];
__device__ float    g_unc2[BATCH * NTASK];
__device__ unsigned g_max2bits;
__device__ float    g_gated[BATCH * NTASK];
__device__ float    g_x0[BATCH * FDIM];
__device__ float    g_x1[BATCH * FDIM];

// ---------------- WMMA tf32 GEMM, 64x64x32 tiles, 4 warps ----------------
// THREE: 3xTF32 error-compensated (fp32-accurate). BCOL: B given as [N,K] row-major
// (i.e. logical B = Bm^T). EPI: 0 = plain store, 1 = +bias[col], 2 = resid + gate*acc.
constexpr int BM = 64, BN = 64, BK = 32;

template <bool THREE, bool BCOL, int EPI>
__global__ void __launch_bounds__(128) gemm_wmma(
    const float* __restrict__ A, int lda,
    const float* __restrict__ Bm, int ldb,
    float* __restrict__ C, int ldc,
    int Kdim,
    const float* __restrict__ bias,
    const float* __restrict__ resid,
    const float* __restrict__ gate, int gcol)
{
    __shared__ __align__(16) float As[BM * (BK + 4)];   // ld 36
    __shared__ __align__(16) float Bs[BN * (BK + 4)];   // ld 36 (BCOL) or 68 (row)
    __shared__ __align__(16) float St[BM * (BN + 4)];   // ld 68

    const int tid = threadIdx.x;
    const int m0 = blockIdx.y * BM;
    const int n0 = blockIdx.x * BN;
    const int warp = tid >> 5;
    const int wm = warp >> 1, wn = warp & 1;

    wmma::fragment<wmma::accumulator, 16, 16, 8, float> acc[2][2];
#pragma unroll
    for (int i = 0; i < 2; i++)
#pragma unroll
        for (int j = 0; j < 2; j++) wmma::fill_fragment(acc[i][j], 0.0f);

    for (int k0 = 0; k0 < Kdim; k0 += BK) {
        // A tile: 64 rows x 32 cols = 512 float4
#pragma unroll
        for (int it = 0; it < 4; it++) {
            int e = it * 128 + tid;
            int r = e >> 3, c = (e & 7) << 2;
            *(float4*)&As[r * 36 + c] =
                *(const float4*)&A[(size_t)(m0 + r) * lda + k0 + c];
        }
        if (BCOL) {
            // B^T tile: 64 n-rows x 32 k = 512 float4
#pragma unroll
            for (int it = 0; it < 4; it++) {
                int e = it * 128 + tid;
                int r = e >> 3, c = (e & 7) << 2;
                *(float4*)&Bs[r * 36 + c] =
                    *(const float4*)&Bm[(size_t)(n0 + r) * ldb + k0 + c];
            }
        } else {
            // B tile: 32 k-rows x 64 n = 512 float4
#pragma unroll
            for (int it = 0; it < 4; it++) {
                int e = it * 128 + tid;
                int r = e >> 4, c = (e & 15) << 2;
                *(float4*)&Bs[r * 68 + c] =
                    *(const float4*)&Bm[(size_t)(k0 + r) * ldb + n0 + c];
            }
        }
        __syncthreads();

#pragma unroll
        for (int kk = 0; kk < BK / 8; kk++) {
            wmma::fragment<wmma::matrix_a, 16, 16, 8, wmma::precision::tf32, wmma::row_major> ah[2], al[2];
#pragma unroll
            for (int i = 0; i < 2; i++) {
                wmma::load_matrix_sync(ah[i], &As[(wm * 32 + i * 16) * 36 + kk * 8], 36);
                if (THREE) {
#pragma unroll
                    for (int e = 0; e < ah[i].num_elements; e++) {
                        float v = ah[i].x[e];
                        float hi = wmma::__float_to_tf32(v);
                        al[i].x[e] = wmma::__float_to_tf32(v - hi);
                        ah[i].x[e] = hi;
                    }
                } else {
#pragma unroll
                    for (int e = 0; e < ah[i].num_elements; e++)
                        ah[i].x[e] = wmma::__float_to_tf32(ah[i].x[e]);
                }
            }
            if constexpr (BCOL) {
                wmma::fragment<wmma::matrix_b, 16, 16, 8, wmma::precision::tf32, wmma::col_major> bh[2], bl[2];
#pragma unroll
                for (int j = 0; j < 2; j++) {
                    wmma::load_matrix_sync(bh[j], &Bs[(wn * 32 + j * 16) * 36 + kk * 8], 36);
                    if (THREE) {
#pragma unroll
                        for (int e = 0; e < bh[j].num_elements; e++) {
                            float v = bh[j].x[e];
                            float hi = wmma::__float_to_tf32(v);
                            bl[j].x[e] = wmma::__float_to_tf32(v - hi);
                            bh[j].x[e] = hi;
                        }
                    } else {
#pragma unroll
                        for (int e = 0; e < bh[j].num_elements; e++)
                            bh[j].x[e] = wmma::__float_to_tf32(bh[j].x[e]);
                    }
                }
#pragma unroll
                for (int i = 0; i < 2; i++)
#pragma unroll
                    for (int j = 0; j < 2; j++) {
                        if (THREE) {
                            wmma::mma_sync(acc[i][j], al[i], bh[j], acc[i][j]);
                            wmma::mma_sync(acc[i][j], ah[i], bl[j], acc[i][j]);
                        }
                        wmma::mma_sync(acc[i][j], ah[i], bh[j], acc[i][j]);
                    }
            } else {
                wmma::fragment<wmma::matrix_b, 16, 16, 8, wmma::precision::tf32, wmma::row_major> bh[2], bl[2];
#pragma unroll
                for (int j = 0; j < 2; j++) {
                    wmma::load_matrix_sync(bh[j], &Bs[(kk * 8) * 68 + wn * 32 + j * 16], 68);
                    if (THREE) {
#pragma unroll
                        for (int e = 0; e < bh[j].num_elements; e++) {
                            float v = bh[j].x[e];
                            float hi = wmma::__float_to_tf32(v);
                            bl[j].x[e] = wmma::__float_to_tf32(v - hi);
                            bh[j].x[e] = hi;
                        }
                    } else {
#pragma unroll
                        for (int e = 0; e < bh[j].num_elements; e++)
                            bh[j].x[e] = wmma::__float_to_tf32(bh[j].x[e]);
                    }
                }
#pragma unroll
                for (int i = 0; i < 2; i++)
#pragma unroll
                    for (int j = 0; j < 2; j++) {
                        if (THREE) {
                            wmma::mma_sync(acc[i][j], al[i], bh[j], acc[i][j]);
                            wmma::mma_sync(acc[i][j], ah[i], bl[j], acc[i][j]);
                        }
                        wmma::mma_sync(acc[i][j], ah[i], bh[j], acc[i][j]);
                    }
            }
        }
        __syncthreads();
    }

    // stage accumulators to smem, apply epilogue with coalesced stores
#pragma unroll
    for (int i = 0; i < 2; i++)
#pragma unroll
        for (int j = 0; j < 2; j++)
            wmma::store_matrix_sync(&St[(wm * 32 + i * 16) * 68 + wn * 32 + j * 16],
                                    acc[i][j], 68, wmma::mem_row_major);
    __syncthreads();
#pragma unroll
    for (int it = 0; it < 32; it++) {
        int e = it * 128 + tid;
        int r = e >> 6, c = e & 63;
        float v = St[r * 68 + c];
        int row = m0 + r, col = n0 + c;
        if (EPI == 1) {
            v += bias[col];
        } else if (EPI == 2) {
            v = resid[(size_t)row * ldc + col] + gate[row * NTASK + gcol] * v;
        }
        C[(size_t)row * ldc + col] = v;
    }
}

// ---------------- coeffs = relu(h) @ W2^T + b2 ----------------
__global__ void coeffs_kernel(const float* __restrict__ W2, const float* __restrict__ b2)
{
    int tid = threadIdx.x;
    int row = blockIdx.x * 32 + (tid >> 3);
    int k = tid & 7;
    const float* hr = g_h + (size_t)row * HDIM;
    const float* w = W2 + k * HDIM;
    float s = b2[k];
#pragma unroll 8
    for (int h = 0; h < HDIM; h++) s += fmaxf(hr[h], 0.0f) * w[h];
    g_coeffs[row * NTASK + k] = s;
}

// ---------------- init global max ----------------
__global__ void init_kernel() { g_max2bits = 0u; }

// ---------------- unc^2[b,k] = a^T G a,  a[h] = W2[k,h] * (h[b,h] > 0) ----------------
// warp per row, lanes over h' (chunks of 32), uniform mask-skip on inner h loop.
__global__ void __launch_bounds__(256) unc_kernel(const float* __restrict__ W2)
{
    __shared__ float W2s[NTASK * HDIM];
    __shared__ float Gs[HDIM * 32];
    int tid = threadIdx.x, lane = tid & 31, warp = tid >> 5;
    for (int i = tid; i < NTASK * HDIM; i += 256) W2s[i] = W2[i];

    int row = blockIdx.x * 8 + warp;
    const float* hr = g_h + (size_t)row * HDIM;
    unsigned mb[8];
#pragma unroll
    for (int j = 0; j < 8; j++)
        mb[j] = __ballot_sync(0xffffffffu, hr[j * 32 + lane] > 0.0f);

    float u2[8];
#pragma unroll
    for (int k = 0; k < 8; k++) u2[k] = 0.0f;

    for (int c = 0; c < 8; c++) {
        __syncthreads();
        for (int i = tid; i < HDIM * 32; i += 256) {
            int h = i >> 5, l = i & 31;
            Gs[i] = g_G[h * HDIM + c * 32 + l];
        }
        __syncthreads();
        float t[8];
#pragma unroll
        for (int k = 0; k < 8; k++) t[k] = 0.0f;
        for (int h = 0; h < HDIM; h++) {
            if ((mb[h >> 5] >> (h & 31)) & 1u) {     // warp-uniform branch
                float gv = Gs[h * 32 + lane];
#pragma unroll
                for (int k = 0; k < 8; k++) t[k] += W2s[k * HDIM + h] * gv;
            }
        }
        int hp = c * 32 + lane;
        if ((mb[hp >> 5] >> (hp & 31)) & 1u) {
#pragma unroll
            for (int k = 0; k < 8; k++) u2[k] += W2s[k * HDIM + hp] * t[k];
        }
    }
#pragma unroll
    for (int k = 0; k < 8; k++) {
        float v = u2[k];
        for (int off = 16; off; off >>= 1) v += __shfl_down_sync(0xffffffffu, v, off);
        if (lane == 0) {
            v = fmaxf(v, 0.0f);
            g_unc2[row * NTASK + k] = v;
            atomicMax(&g_max2bits, __float_as_uint(v));   // v >= 0: uint order == float order
        }
    }
}

// ---------------- gating ----------------
__global__ void gate_kernel(const float* __restrict__ bthr, const float* __restrict__ beta)
{
    int i = blockIdx.x * blockDim.x + threadIdx.x;
    if (i >= BATCH * NTASK) return;
    float max2 = __uint_as_float(g_max2bits);
    float u = (max2 > 0.0f) ? sqrtf(g_unc2[i] / max2) : sqrtf(g_unc2[i]);
    float base = log1pf(expf(bthr[0]));          // softplus
    float thr = base * (1.0f + fmaxf(beta[0], 0.0f) * u);
    float cf = g_coeffs[i];
    g_gated[i] = (fabsf(cf) < thr) ? 0.0f : cf;
}

// ---------------- launch ----------------
extern "C" void kernel_launch(void* const* d_in, const int* in_sizes, int n_in,
                              void* d_out, int out_size)
{
    const float* features = (const float*)d_in[0];
    const float* W1   = (const float*)d_in[1];
    const float* b1   = (const float*)d_in[2];
    const float* W2   = (const float*)d_in[3];
    const float* b2   = (const float*)d_in[4];
    const float* task = (const float*)d_in[5];
    const float* projW = (const float*)d_in[6];
    const float* bthr = (const float*)d_in[7];
    const float* beta = (const float*)d_in[8];
    float* out = (float*)d_out;

    float *hbuf, *Gbuf, *x0, *x1, *gated;
    cudaGetSymbolAddress((void**)&hbuf, g_h);
    cudaGetSymbolAddress((void**)&Gbuf, g_G);
    cudaGetSymbolAddress((void**)&x0, g_x0);
    cudaGetSymbolAddress((void**)&x1, g_x1);
    cudaGetSymbolAddress((void**)&gated, g_gated);

    dim3 blk(128);

    // h = F @ W1^T + b1   (3xTF32: mask-accurate)
    gemm_wmma<true, true, 1><<<dim3(HDIM / 64, BATCH / 64), blk>>>(
        features, FDIM, W1, FDIM, hbuf, HDIM, FDIM, b1, nullptr, nullptr, 0);

    // G = W1 @ W1^T       (3xTF32)
    gemm_wmma<true, true, 0><<<dim3(HDIM / 64, HDIM / 64), blk>>>(
        W1, FDIM, W1, FDIM, Gbuf, HDIM, FDIM, nullptr, nullptr, nullptr, 0);

    coeffs_kernel<<<BATCH / 32, 256>>>(W2, b2);
    init_kernel<<<1, 1>>>();
    unc_kernel<<<BATCH / 8, 256>>>(W2);
    gate_kernel<<<(BATCH * NTASK + 255) / 256, 256>>>(bthr, beta);

    // sequential task-vector chain (1xTF32, corrections only)
    const float* xin = features;
    float* xout = x0;
    for (int j = 0; j < NTASK; j++) {
        gemm_wmma<false, false, 2><<<dim3(FDIM / 64, BATCH / 64), blk>>>(
            xin, FDIM, task + (size_t)j * FDIM * FDIM, FDIM,
            xout, FDIM, FDIM, nullptr, xin, gated, j);
        xin = xout;
        xout = (xout == x0) ? x1 : x0;
    }

    // out = x @ proj_W^T  (3xTF32: proj ~ identity, must not truncate x)
    gemm_wmma<true, true, 0><<<dim3(FDIM / 64, BATCH / 64), blk>>>(
        xin, FDIM, projW, FDIM, out, FDIM, FDIM, nullptr, nullptr, nullptr, 0);
}